// round 15
// baseline (speedup 1.0000x reference)
#include <cuda_runtime.h>
#include <cuda_bf16.h>
#include <cstddef>
#include <cstdint>

// ---------------------------------------------------------------------------
// GCN_ValueNet: 3-layer GCN (128->128->64->1) + final dot with W4.
//   g = X@W  raw, via bf16x3 emulated-fp32 GEMM on m16n8k16 bf16 tensor cores:
//     x = h + m,  h = bf16(x), m = bf16(x - h)  (residual ~2^-18)
//     D += ah*bh + am*bh + ah*bm    (fp32 accumulate)
//   GEMM: 256 thr / 8 warps (4Mx2N), warp tile 32x32 -> 4 warps/SMSP.
//   gathers apply symmetric normalization per-edge.
//   CSR build (bucket, cap 64) on a SIDE STREAM hidden under gemm1.
//   Dependent kernels use PDL (griddepcontrol.wait) to absorb launch gaps.
// edge_index arrives as int32 (JAX x64 disabled).
// NOTE: tcgen05 unavailable (harness PTX target is compute_103, no 'a').
// ---------------------------------------------------------------------------

#define MAX_NODES 50016
#define BUCKET_CAP 64

__device__ int   g_cnt[MAX_NODES];
__device__ int   g_col[MAX_NODES * BUCKET_CAP];
__device__ float g_dinv[MAX_NODES];
__device__ float g_bufA[MAX_NODES * 128];
__device__ float g_bufB[MAX_NODES * 128];
__device__ float g_bufC[MAX_NODES * 128];
__device__ float g_partials[256];

__device__ __forceinline__ void pdl_wait() {
    asm volatile("griddepcontrol.wait;" ::: "memory");
}

// Pack two consecutive elements (x0 = even-k, x1 = odd-k) into (h, m) bf16x2.
__device__ __forceinline__ uint2 pack_hm(float x0, float x1) {
    uint32_t hp;
    asm("cvt.rn.bf16x2.f32 %0, %1, %2;" : "=r"(hp) : "f"(x1), "f"(x0));
    float h0 = __uint_as_float(hp << 16);
    float h1 = __uint_as_float(hp & 0xFFFF0000u);
    uint32_t mp;
    asm("cvt.rn.bf16x2.f32 %0, %1, %2;" : "=r"(mp) : "f"(x1 - h1), "f"(x0 - h0));
    return make_uint2(hp, mp);
}

__device__ __forceinline__ void mma_bf16(float* d, const uint32_t* a,
                                         const uint32_t* b, const float* c) {
    asm("mma.sync.aligned.m16n8k16.row.col.f32.bf16.bf16.f32 "
        "{%0,%1,%2,%3},{%4,%5,%6,%7},{%8,%9},{%10,%11,%12,%13};"
        : "=f"(d[0]), "=f"(d[1]), "=f"(d[2]), "=f"(d[3])
        : "r"(a[0]), "r"(a[1]), "r"(a[2]), "r"(a[3]),
          "r"(b[0]), "r"(b[1]),
          "f"(c[0]), "f"(c[1]), "f"(c[2]), "f"(c[3]));
}

// ---------------- bucket-CSR build ----------------
__global__ void k_zero_int(int* p, int n) {
    int i = blockIdx.x * blockDim.x + threadIdx.x;
    if (i < n) p[i] = 0;
}

__global__ void k_fillcount(const int* __restrict__ src, const int* __restrict__ dst,
                            int E, int* __restrict__ cnt, int* __restrict__ col) {
    int i = blockIdx.x * blockDim.x + threadIdx.x;
    if (i >= E) return;
    int d = dst[i];
    int slot = atomicAdd(&cnt[d], 1);
    if (slot < BUCKET_CAP) col[d * BUCKET_CAP + slot] = src[i];
}

__global__ void k_dinv(const int* __restrict__ cnt, float* __restrict__ dinv, int n) {
    int i = blockIdx.x * blockDim.x + threadIdx.x;
    if (i < n) dinv[i] = rsqrtf((float)cnt[i] + 1.0f);
}

// ------- bf16x3 GEMM: out[r][col0+c] = A[r][:128] . W[:][col0+c] ------------
// BM=128, BN=64 per CTA (blockIdx.y = col block), BK=16.
// 256 threads = 8 warps as 4(M) x 2(N); warp tile 32x32 = 2 mtiles x 4 ntiles.
__global__ __launch_bounds__(256, 2) void k_gemm_bf16x3(const float* __restrict__ A,
                                                        const float* __restrict__ W,
                                                        float* __restrict__ out,
                                                        int M, int ldN) {
    constexpr int BM = 128, BN = 64, BK = 16, K = 128;
    constexpr int SAS = 10;   // uint2/row: 8 k-pairs + 2 pad
    constexpr int SBS = 68;   // uint2/k-pair row: 64 n + 4 pad
    __shared__ uint2 sA[BM][SAS];      // 10.0 KB
    __shared__ uint2 sB[BK / 2][SBS];  //  4.25 KB

    pdl_wait();   // no-op when launched without the PDL attribute

    const int tid    = threadIdx.x;
    const int wid    = tid >> 5;
    const int lane   = tid & 31;
    const int warp_m = wid & 3;     // 0..3
    const int warp_n = wid >> 2;    // 0..1
    const int row0   = blockIdx.x * BM;
    const int col0   = blockIdx.y * BN;

    float acc[2][4][4];
#pragma unroll
    for (int m = 0; m < 2; m++)
#pragma unroll
        for (int n = 0; n < 4; n++)
#pragma unroll
            for (int q = 0; q < 4; q++) acc[m][n][q] = 0.0f;

    // A gmem mapping: 2 passes of 64 rows; one float4 (4 k) per pass
    const int aRow  = tid >> 2;           // 0..63
    const int aColE = (tid & 3) * 4;      // element k-offset 0,4,8,12
    const int aPair = (tid & 3) * 2;      // pair index 0,2,4,6
    // B gmem mapping (first 128 threads): kp = tid>>4 (0..7), 4 n's each
    const int bKp = (tid & 127) >> 4;
    const int bN0 = (tid & 15) * 4;
    const bool bAct = tid < 128;

    bool aOk[2];
    const float* aP[2];
#pragma unroll
    for (int p = 0; p < 2; p++) {
        int r = row0 + aRow + p * 64;
        aOk[p] = r < M;
        aP[p]  = A + (size_t)r * K + aColE;
    }
    const float* bP0 = W + (size_t)(2 * bKp)     * ldN + col0 + bN0;
    const float* bP1 = W + (size_t)(2 * bKp + 1) * ldN + col0 + bN0;

    const int lq = lane >> 2;             // 0..7
    const int lr = lane & 3;              // 0..3

    // ---- prefetch kt = 0 ----
    float4 pa[2], pb0, pb1;
#pragma unroll
    for (int p = 0; p < 2; p++) {
        pa[p] = make_float4(0.f, 0.f, 0.f, 0.f);
        if (aOk[p]) pa[p] = *(const float4*)aP[p];
    }
    pb0 = make_float4(0.f, 0.f, 0.f, 0.f);
    pb1 = pb0;
    if (bAct) { pb0 = *(const float4*)bP0; pb1 = *(const float4*)bP1; }

#pragma unroll
    for (int kt = 0; kt < K / BK; kt++) {
        // split + store prefetched tile (uint4 = two (h,m) uint2s)
#pragma unroll
        for (int p = 0; p < 2; p++) {
            uint2 e0 = pack_hm(pa[p].x, pa[p].y);
            uint2 e1 = pack_hm(pa[p].z, pa[p].w);
            *(uint4*)&sA[aRow + p * 64][aPair] = make_uint4(e0.x, e0.y, e1.x, e1.y);
        }
        if (bAct) {
            uint2 e0 = pack_hm(pb0.x, pb1.x);
            uint2 e1 = pack_hm(pb0.y, pb1.y);
            uint2 e2 = pack_hm(pb0.z, pb1.z);
            uint2 e3 = pack_hm(pb0.w, pb1.w);
            *(uint4*)&sB[bKp][bN0    ] = make_uint4(e0.x, e0.y, e1.x, e1.y);
            *(uint4*)&sB[bKp][bN0 + 2] = make_uint4(e2.x, e2.y, e3.x, e3.y);
        }
        __syncthreads();

        if (kt < K / BK - 1) {
            const int k0 = (kt + 1) * BK;
#pragma unroll
            for (int p = 0; p < 2; p++) {
                pa[p] = make_float4(0.f, 0.f, 0.f, 0.f);
                if (aOk[p]) pa[p] = *(const float4*)(aP[p] + k0);
            }
            if (bAct) {
                pb0 = *(const float4*)(bP0 + (size_t)k0 * ldN);
                pb1 = *(const float4*)(bP1 + (size_t)k0 * ldN);
            }
        }

        // one m16n8k16 step covers the whole BK=16 tile
        {
            uint32_t ah[2][4], am[2][4], bh[4][2], bm[4][2];
#pragma unroll
            for (int m = 0; m < 2; m++) {
                int r = warp_m * 32 + m * 16 + lq;
                uint2 q0 = sA[r    ][lr    ];
                uint2 q1 = sA[r + 8][lr    ];
                uint2 q2 = sA[r    ][lr + 4];
                uint2 q3 = sA[r + 8][lr + 4];
                ah[m][0] = q0.x; ah[m][1] = q1.x; ah[m][2] = q2.x; ah[m][3] = q3.x;
                am[m][0] = q0.y; am[m][1] = q1.y; am[m][2] = q2.y; am[m][3] = q3.y;
            }
#pragma unroll
            for (int n = 0; n < 4; n++) {
                int c = warp_n * 32 + n * 8 + lq;
                uint2 p0 = sB[lr    ][c];
                uint2 p1 = sB[lr + 4][c];
                bh[n][0] = p0.x; bh[n][1] = p1.x;
                bm[n][0] = p0.y; bm[n][1] = p1.y;
            }
#pragma unroll
            for (int n = 0; n < 4; n++)
#pragma unroll
                for (int m = 0; m < 2; m++)
                    mma_bf16(acc[m][n], ah[m], bh[n], acc[m][n]);
#pragma unroll
            for (int n = 0; n < 4; n++)
#pragma unroll
                for (int m = 0; m < 2; m++)
                    mma_bf16(acc[m][n], am[m], bh[n], acc[m][n]);
#pragma unroll
            for (int n = 0; n < 4; n++)
#pragma unroll
                for (int m = 0; m < 2; m++)
                    mma_bf16(acc[m][n], ah[m], bm[n], acc[m][n]);
        }
        __syncthreads();
    }

    // epilogue: store raw g (normalization applied in the gather kernels)
#pragma unroll
    for (int m = 0; m < 2; m++) {
        int r0 = row0 + warp_m * 32 + m * 16 + lq;
        int r1 = r0 + 8;
#pragma unroll
        for (int n = 0; n < 4; n++) {
            int c = col0 + warp_n * 32 + n * 8 + lr * 2;
            if (r0 < M) {
                float2 v; v.x = acc[m][n][0]; v.y = acc[m][n][1];
                *(float2*)(out + (size_t)r0 * ldN + c) = v;
            }
            if (r1 < M) {
                float2 v; v.x = acc[m][n][2]; v.y = acc[m][n][3];
                *(float2*)(out + (size_t)r1 * ldN + c) = v;
            }
        }
    }
}

// ------- layer-1 gather + fused activation (C=128), per-edge dinv scale ----
__global__ void k_gather_act128(const float* __restrict__ g, const int* __restrict__ col,
                                const int* __restrict__ cnt, const float* __restrict__ dinv,
                                const float* __restrict__ bias,
                                float* __restrict__ out, int N) {
    int warp = (blockIdx.x * blockDim.x + threadIdx.x) >> 5;
    int lane = threadIdx.x & 31;
    pdl_wait();
    if (warp >= N) return;
    const int* bucket = col + (size_t)warp * BUCKET_CAP;
    int m = cnt[warp];
    if (m > BUCKET_CAP) m = BUCKET_CAP;

    float4 acc = make_float4(0.f, 0.f, 0.f, 0.f);
    int e = 0;
    for (; e + 4 <= m; e += 4) {
        int s0 = __ldg(&bucket[e + 0]);
        int s1 = __ldg(&bucket[e + 1]);
        int s2 = __ldg(&bucket[e + 2]);
        int s3 = __ldg(&bucket[e + 3]);
        float d0 = __ldg(&dinv[s0]);
        float d1 = __ldg(&dinv[s1]);
        float d2 = __ldg(&dinv[s2]);
        float d3 = __ldg(&dinv[s3]);
        float4 v0 = *((const float4*)(g + (size_t)s0 * 128) + lane);
        float4 v1 = *((const float4*)(g + (size_t)s1 * 128) + lane);
        float4 v2 = *((const float4*)(g + (size_t)s2 * 128) + lane);
        float4 v3 = *((const float4*)(g + (size_t)s3 * 128) + lane);
        acc.x += d0 * v0.x + d1 * v1.x + d2 * v2.x + d3 * v3.x;
        acc.y += d0 * v0.y + d1 * v1.y + d2 * v2.y + d3 * v3.y;
        acc.z += d0 * v0.z + d1 * v1.z + d2 * v2.z + d3 * v3.z;
        acc.w += d0 * v0.w + d1 * v1.w + d2 * v2.w + d3 * v3.w;
    }
    for (; e < m; e++) {
        int s = __ldg(&bucket[e]);
        float d = __ldg(&dinv[s]);
        float4 v = *((const float4*)(g + (size_t)s * 128) + lane);
        acc.x += d * v.x; acc.y += d * v.y; acc.z += d * v.z; acc.w += d * v.w;
    }
    float4 self = *((const float4*)(g + (size_t)warp * 128) + lane);
    float  dv = dinv[warp];
    float4 bb = *((const float4*)bias + lane);
    float4 r;
    r.x = tanhf((acc.x + dv * self.x) * dv + bb.x);
    r.y = tanhf((acc.y + dv * self.y) * dv + bb.y);
    r.z = tanhf((acc.z + dv * self.z) * dv + bb.z);
    r.w = tanhf((acc.w + dv * self.w) * dv + bb.w);
    *((float4*)(out + (size_t)warp * 128) + lane) = r;
}

// ------- layer-2 gather + activation + FUSED W3 matvec (C=64) --------------
__global__ void k_gather_act64_mv(const float* __restrict__ g, const int* __restrict__ col,
                                  const int* __restrict__ cnt, const float* __restrict__ dinv,
                                  const float* __restrict__ bias,
                                  const float* __restrict__ W3,
                                  float* __restrict__ u3, int N) {
    int warp = (blockIdx.x * blockDim.x + threadIdx.x) >> 5;
    int lane = threadIdx.x & 31;
    pdl_wait();
    if (warp >= N) return;
    const int* bucket = col + (size_t)warp * BUCKET_CAP;
    int m = cnt[warp];
    if (m > BUCKET_CAP) m = BUCKET_CAP;

    float2 acc = make_float2(0.f, 0.f);
    int e = 0;
    for (; e + 4 <= m; e += 4) {
        int s0 = __ldg(&bucket[e + 0]);
        int s1 = __ldg(&bucket[e + 1]);
        int s2 = __ldg(&bucket[e + 2]);
        int s3 = __ldg(&bucket[e + 3]);
        float d0 = __ldg(&dinv[s0]);
        float d1 = __ldg(&dinv[s1]);
        float d2 = __ldg(&dinv[s2]);
        float d3 = __ldg(&dinv[s3]);
        float2 v0 = *((const float2*)(g + (size_t)s0 * 64) + lane);
        float2 v1 = *((const float2*)(g + (size_t)s1 * 64) + lane);
        float2 v2 = *((const float2*)(g + (size_t)s2 * 64) + lane);
        float2 v3 = *((const float2*)(g + (size_t)s3 * 64) + lane);
        acc.x += d0 * v0.x + d1 * v1.x + d2 * v2.x + d3 * v3.x;
        acc.y += d0 * v0.y + d1 * v1.y + d2 * v2.y + d3 * v3.y;
    }
    for (; e < m; e++) {
        int s = __ldg(&bucket[e]);
        float d = __ldg(&dinv[s]);
        float2 v = *((const float2*)(g + (size_t)s * 64) + lane);
        acc.x += d * v.x; acc.y += d * v.y;
    }
    float2 self = *((const float2*)(g + (size_t)warp * 64) + lane);
    float  dv = dinv[warp];
    float2 bb = *((const float2*)bias + lane);
    float hx = tanhf((acc.x + dv * self.x) * dv + bb.x);
    float hy = tanhf((acc.y + dv * self.y) * dv + bb.y);
    float2 w = *((const float2*)W3 + lane);
    float s = hx * w.x + hy * w.y;
#pragma unroll
    for (int o = 16; o; o >>= 1) s += __shfl_xor_sync(0xFFFFFFFFu, s, o);
    if (lane == 0) u3[warp] = s * dv;   // u3 = dinv * (h2 . W3)
}

// ------- layer3 gather + activation + dot with W4 --------------------------
__global__ void k_gather3_dot(const float* __restrict__ u3, const int* __restrict__ col,
                              const int* __restrict__ cnt, const float* __restrict__ dinv,
                              const float* __restrict__ b3,
                              const float* __restrict__ W4, float* __restrict__ partials,
                              int N) {
    __shared__ float sm[256];
    int i = blockIdx.x * 256 + threadIdx.x;
    pdl_wait();
    float contrib = 0.0f;
    if (i < N) {
        const int* bucket = col + (size_t)i * BUCKET_CAP;
        int m = cnt[i];
        if (m > BUCKET_CAP) m = BUCKET_CAP;
        float acc = 0.0f;
        for (int e = 0; e < m; e++) acc += u3[__ldg(&bucket[e])];
        float v = tanhf((acc + u3[i]) * dinv[i] + b3[0]);
        contrib = W4[i] * v;
    }
    sm[threadIdx.x] = contrib;
    __syncthreads();
    for (int s = 128; s; s >>= 1) {
        if (threadIdx.x < s) sm[threadIdx.x] += sm[threadIdx.x + s];
        __syncthreads();
    }
    if (threadIdx.x == 0) partials[blockIdx.x] = sm[0];
}

__global__ void k_final_reduce(const float* __restrict__ partials,
                               const float* __restrict__ b4,
                               float* __restrict__ out, int nb) {
    __shared__ float sm[256];
    pdl_wait();
    sm[threadIdx.x] = (threadIdx.x < nb) ? partials[threadIdx.x] : 0.0f;
    __syncthreads();
    for (int s = 128; s; s >>= 1) {
        if (threadIdx.x < s) sm[threadIdx.x] += sm[threadIdx.x + s];
        __syncthreads();
    }
    if (threadIdx.x == 0) out[0] = sm[0] + b4[0];
}

// ---------------------------------------------------------------------------
extern "C" void kernel_launch(void* const* d_in, const int* in_sizes, int n_in,
                              void* d_out, int out_size) {
    const float* x   = (const float*)d_in[0];
    const int*   ei  = (const int*)d_in[1];
    const float* W1  = (const float*)d_in[2];
    const float* b1  = (const float*)d_in[3];
    const float* W2  = (const float*)d_in[4];
    const float* b2  = (const float*)d_in[5];
    const float* W3  = (const float*)d_in[6];
    const float* b3  = (const float*)d_in[7];
    const float* W4  = (const float*)d_in[8];
    const float* b4  = (const float*)d_in[9];

    int N = in_sizes[0] / 128;
    int E = in_sizes[1] / 2;
    const int* src = ei;
    const int* dst = ei + E;

    int *cnt, *col;
    float *dinv, *bufA, *bufB, *bufC, *partials;
    cudaGetSymbolAddress((void**)&cnt, g_cnt);
    cudaGetSymbolAddress((void**)&col, g_col);
    cudaGetSymbolAddress((void**)&dinv, g_dinv);
    cudaGetSymbolAddress((void**)&bufA, g_bufA);
    cudaGetSymbolAddress((void**)&bufB, g_bufB);
    cudaGetSymbolAddress((void**)&bufC, g_bufC);
    cudaGetSymbolAddress((void**)&partials, g_partials);

    const int nBlkN = (N + 255) / 256;
    const int rowBlk = (N + 127) / 128;

    // One-time side stream + fork/join events (infrastructure, not work).
    static cudaStream_t s_side = nullptr;
    static cudaEvent_t  ev_fork = nullptr, ev_join = nullptr;
    if (s_side == nullptr) {
        cudaStreamCreateWithFlags(&s_side, cudaStreamNonBlocking);
        cudaEventCreateWithFlags(&ev_fork, cudaEventDisableTiming);
        cudaEventCreateWithFlags(&ev_join, cudaEventDisableTiming);
    }

    // PDL launch config (programmatic serialization with stream predecessor)
    cudaLaunchAttribute pdlAttr[1];
    pdlAttr[0].id = cudaLaunchAttributeProgrammaticStreamSerialization;
    pdlAttr[0].val.programmaticStreamSerializationAllowed = 1;

    // ---- fork: CSR build on side stream, gemm1 on main stream ----
    cudaEventRecord(ev_fork, 0);
    cudaStreamWaitEvent(s_side, ev_fork, 0);
    k_zero_int<<<nBlkN, 256, 0, s_side>>>(cnt, N);
    k_fillcount<<<(E + 255) / 256, 256, 0, s_side>>>(src, dst, E, cnt, col);
    k_dinv<<<nBlkN, 256, 0, s_side>>>(cnt, dinv, N);
    cudaEventRecord(ev_join, s_side);

    // ---- layer 1 (128 -> 128), independent of CSR ----
    k_gemm_bf16x3<<<dim3(rowBlk, 2), 256>>>(x, W1, bufA, N, 128);           // g1

    // ---- join: gathers need CSR ----
    cudaStreamWaitEvent(0, ev_join, 0);
    {
        cudaLaunchConfig_t cfg = {};
        cfg.gridDim = dim3((N * 32 + 255) / 256);
        cfg.blockDim = dim3(256);
        cfg.attrs = pdlAttr; cfg.numAttrs = 1;
        cudaLaunchKernelEx(&cfg, k_gather_act128, bufA, (const int*)col,
                           (const int*)cnt, (const float*)dinv, b1, bufB, N);  // h1
    }

    // ---- layer 2 (128 -> 64) + fused layer-3 matvec ----
    {
        cudaLaunchConfig_t cfg = {};
        cfg.gridDim = dim3(rowBlk, 1);
        cfg.blockDim = dim3(256);
        cfg.attrs = pdlAttr; cfg.numAttrs = 1;
        cudaLaunchKernelEx(&cfg, k_gemm_bf16x3, (const float*)bufB, W2, bufC, N, 64);  // g2
    }
    {
        cudaLaunchConfig_t cfg = {};
        cfg.gridDim = dim3((N * 32 + 255) / 256);
        cfg.blockDim = dim3(256);
        cfg.attrs = pdlAttr; cfg.numAttrs = 1;
        cudaLaunchKernelEx(&cfg, k_gather_act64_mv, (const float*)bufC, (const int*)col,
                           (const int*)cnt, (const float*)dinv, b2, W3, bufA, N);  // u3
    }

    // ---- layer 3 aggregation + final dot ----
    {
        cudaLaunchConfig_t cfg = {};
        cfg.gridDim = dim3(nBlkN);
        cfg.blockDim = dim3(256);
        cfg.attrs = pdlAttr; cfg.numAttrs = 1;
        cudaLaunchKernelEx(&cfg, k_gather3_dot, (const float*)bufA, (const int*)col,
                           (const int*)cnt, (const float*)dinv, b3, W4, partials, N);
    }
    {
        cudaLaunchConfig_t cfg = {};
        cfg.gridDim = dim3(1);
        cfg.blockDim = dim3(256);
        cfg.attrs = pdlAttr; cfg.numAttrs = 1;
        cudaLaunchKernelEx(&cfg, k_final_reduce, (const float*)partials, b4,
                           (float*)d_out, nBlkN);
    }
}

// round 16
// speedup vs baseline: 1.0919x; 1.0919x over previous
#include <cuda_runtime.h>
#include <cuda_bf16.h>
#include <cstddef>
#include <cstdint>

// ---------------------------------------------------------------------------
// GCN_ValueNet: 3-layer GCN (128->128->64->1) + final dot with W4.
//   g = X@W  raw, via bf16x3 emulated-fp32 GEMM on m16n8k16 bf16 tensor cores:
//     x = h + m,  h = bf16(x), m = bf16(x - h)  (residual ~2^-18)
//     D += ah*bh + am*bh + ah*bm    (fp32 accumulate, phase-ordered)
//   GEMM: 128 thr / 4 warps (2Mx2N), warp tile 64x32 (measured-best config).
//   gathers apply symmetric normalization per-edge.
//   CSR build (bucket, cap 64) on a SIDE STREAM hidden under gemm1; k_dinv
//   also seeds d_out[0] = b4[0] so the last gather atomically accumulates
//   the final dot directly into d_out (no separate reduce kernel).
//   Dependent kernels use PDL (griddepcontrol.wait) to absorb launch gaps.
// edge_index arrives as int32 (JAX x64 disabled).
// NOTE: tcgen05 unavailable (harness PTX target is compute_103, no 'a').
// ---------------------------------------------------------------------------

#define MAX_NODES 50016
#define BUCKET_CAP 64

__device__ int   g_cnt[MAX_NODES];
__device__ int   g_col[MAX_NODES * BUCKET_CAP];
__device__ float g_dinv[MAX_NODES];
__device__ float g_bufA[MAX_NODES * 128];
__device__ float g_bufB[MAX_NODES * 128];
__device__ float g_bufC[MAX_NODES * 128];

__device__ __forceinline__ void pdl_wait() {
    asm volatile("griddepcontrol.wait;" ::: "memory");
}

// Pack two consecutive elements (x0 = even-k, x1 = odd-k) into (h, m) bf16x2.
__device__ __forceinline__ uint2 pack_hm(float x0, float x1) {
    uint32_t hp;
    asm("cvt.rn.bf16x2.f32 %0, %1, %2;" : "=r"(hp) : "f"(x1), "f"(x0));
    float h0 = __uint_as_float(hp << 16);
    float h1 = __uint_as_float(hp & 0xFFFF0000u);
    uint32_t mp;
    asm("cvt.rn.bf16x2.f32 %0, %1, %2;" : "=r"(mp) : "f"(x1 - h1), "f"(x0 - h0));
    return make_uint2(hp, mp);
}

__device__ __forceinline__ void mma_bf16(float* d, const uint32_t* a,
                                         const uint32_t* b, const float* c) {
    asm("mma.sync.aligned.m16n8k16.row.col.f32.bf16.bf16.f32 "
        "{%0,%1,%2,%3},{%4,%5,%6,%7},{%8,%9},{%10,%11,%12,%13};"
        : "=f"(d[0]), "=f"(d[1]), "=f"(d[2]), "=f"(d[3])
        : "r"(a[0]), "r"(a[1]), "r"(a[2]), "r"(a[3]),
          "r"(b[0]), "r"(b[1]),
          "f"(c[0]), "f"(c[1]), "f"(c[2]), "f"(c[3]));
}

// ---------------- bucket-CSR build ----------------
__global__ void k_zero_int(int* p, int n) {
    int i = blockIdx.x * blockDim.x + threadIdx.x;
    if (i < n) p[i] = 0;
}

__global__ void k_fillcount(const int* __restrict__ src, const int* __restrict__ dst,
                            int E, int* __restrict__ cnt, int* __restrict__ col) {
    int i = blockIdx.x * blockDim.x + threadIdx.x;
    if (i >= E) return;
    int d = dst[i];
    int slot = atomicAdd(&cnt[d], 1);
    if (slot < BUCKET_CAP) col[d * BUCKET_CAP + slot] = src[i];
}

// dinv + seed d_out[0] = b4[0] (reset every replay; stream order guarantees
// this happens before k_gather3_dot's atomic accumulation).
__global__ void k_dinv(const int* __restrict__ cnt, float* __restrict__ dinv, int n,
                       const float* __restrict__ b4, float* __restrict__ out0) {
    int i = blockIdx.x * blockDim.x + threadIdx.x;
    if (i < n) dinv[i] = rsqrtf((float)cnt[i] + 1.0f);
    if (i == 0) out0[0] = b4[0];
}

// ------- bf16x3 GEMM: out[r][col0+c] = A[r][:128] . W[:][col0+c] ------------
// BM=128, BN=64 per CTA (blockIdx.y = col block), BK=16 (one k16 step per kt).
// 128 threads = 4 warps as 2(M) x 2(N); warp tile 64x32 = 4 mtiles x 4 ntiles.
__global__ __launch_bounds__(128, 3) void k_gemm_bf16x3(const float* __restrict__ A,
                                                        const float* __restrict__ W,
                                                        float* __restrict__ out,
                                                        int M, int ldN) {
    constexpr int BM = 128, BN = 64, BK = 16, K = 128;
    constexpr int SAS = 10;   // uint2/row: 8 k-pairs + 2 pad
    constexpr int SBS = 68;   // uint2/k-pair row: 64 n + 4 pad
    __shared__ uint2 sA[BM][SAS];      // 10.0 KB
    __shared__ uint2 sB[BK / 2][SBS];  //  4.25 KB

    pdl_wait();   // no-op when launched without the PDL attribute

    const int tid    = threadIdx.x;
    const int wid    = tid >> 5;
    const int lane   = tid & 31;
    const int warp_m = wid & 1;
    const int warp_n = wid >> 1;
    const int row0   = blockIdx.x * BM;
    const int col0   = blockIdx.y * BN;

    float acc[4][4][4];
#pragma unroll
    for (int m = 0; m < 4; m++)
#pragma unroll
        for (int n = 0; n < 4; n++)
#pragma unroll
            for (int q = 0; q < 4; q++) acc[m][n][q] = 0.0f;

    const int aRow  = tid >> 2;           // 0..31
    const int aColE = (tid & 3) * 4;      // element k-offset 0,4,8,12
    const int aPair = (tid & 3) * 2;      // pair index 0,2,4,6
    const int bKp = tid >> 4;             // 0..7
    const int bN0 = (tid & 15) * 4;       // 0..60

    bool aOk[4];
    const float* aP[4];
#pragma unroll
    for (int p = 0; p < 4; p++) {
        int r = row0 + aRow + p * 32;
        aOk[p] = r < M;
        aP[p]  = A + (size_t)r * K + aColE;
    }
    const float* bP0 = W + (size_t)(2 * bKp)     * ldN + col0 + bN0;
    const float* bP1 = W + (size_t)(2 * bKp + 1) * ldN + col0 + bN0;

    const int lq = lane >> 2;             // 0..7
    const int lr = lane & 3;              // 0..3

    // ---- prefetch kt = 0 ----
    float4 pa[4], pb0, pb1;
#pragma unroll
    for (int p = 0; p < 4; p++) {
        pa[p] = make_float4(0.f, 0.f, 0.f, 0.f);
        if (aOk[p]) pa[p] = *(const float4*)aP[p];
    }
    pb0 = *(const float4*)bP0;
    pb1 = *(const float4*)bP1;

#pragma unroll
    for (int kt = 0; kt < K / BK; kt++) {
        // split + store prefetched tile (uint4 = two (h,m) uint2s)
#pragma unroll
        for (int p = 0; p < 4; p++) {
            uint2 e0 = pack_hm(pa[p].x, pa[p].y);
            uint2 e1 = pack_hm(pa[p].z, pa[p].w);
            *(uint4*)&sA[aRow + p * 32][aPair] = make_uint4(e0.x, e0.y, e1.x, e1.y);
        }
        {
            uint2 e0 = pack_hm(pb0.x, pb1.x);
            uint2 e1 = pack_hm(pb0.y, pb1.y);
            uint2 e2 = pack_hm(pb0.z, pb1.z);
            uint2 e3 = pack_hm(pb0.w, pb1.w);
            *(uint4*)&sB[bKp][bN0    ] = make_uint4(e0.x, e0.y, e1.x, e1.y);
            *(uint4*)&sB[bKp][bN0 + 2] = make_uint4(e2.x, e2.y, e3.x, e3.y);
        }
        __syncthreads();

        if (kt < K / BK - 1) {
            const int k0 = (kt + 1) * BK;
#pragma unroll
            for (int p = 0; p < 4; p++) {
                pa[p] = make_float4(0.f, 0.f, 0.f, 0.f);
                if (aOk[p]) pa[p] = *(const float4*)(aP[p] + k0);
            }
            pb0 = *(const float4*)(bP0 + (size_t)k0 * ldN);
            pb1 = *(const float4*)(bP1 + (size_t)k0 * ldN);
        }

        // one m16n8k16 step covers the whole BK=16 tile
        {
            uint32_t ah[4][4], am[4][4], bh[4][2], bm[4][2];
#pragma unroll
            for (int m = 0; m < 4; m++) {
                int r = warp_m * 64 + m * 16 + lq;
                uint2 q0 = sA[r    ][lr    ];
                uint2 q1 = sA[r + 8][lr    ];
                uint2 q2 = sA[r    ][lr + 4];
                uint2 q3 = sA[r + 8][lr + 4];
                ah[m][0] = q0.x; ah[m][1] = q1.x; ah[m][2] = q2.x; ah[m][3] = q3.x;
                am[m][0] = q0.y; am[m][1] = q1.y; am[m][2] = q2.y; am[m][3] = q3.y;
            }
#pragma unroll
            for (int n = 0; n < 4; n++) {
                int c = warp_n * 32 + n * 8 + lq;
                uint2 p0 = sB[lr    ][c];
                uint2 p1 = sB[lr + 4][c];
                bh[n][0] = p0.x; bh[n][1] = p1.x;
                bm[n][0] = p0.y; bm[n][1] = p1.y;
            }
#pragma unroll
            for (int n = 0; n < 4; n++)
#pragma unroll
                for (int m = 0; m < 4; m++)
                    mma_bf16(acc[m][n], ah[m], bh[n], acc[m][n]);
#pragma unroll
            for (int n = 0; n < 4; n++)
#pragma unroll
                for (int m = 0; m < 4; m++)
                    mma_bf16(acc[m][n], am[m], bh[n], acc[m][n]);
#pragma unroll
            for (int n = 0; n < 4; n++)
#pragma unroll
                for (int m = 0; m < 4; m++)
                    mma_bf16(acc[m][n], ah[m], bm[n], acc[m][n]);
        }
        __syncthreads();
    }

    // epilogue: store raw g (normalization applied in the gather kernels)
#pragma unroll
    for (int m = 0; m < 4; m++) {
        int r0 = row0 + warp_m * 64 + m * 16 + lq;
        int r1 = r0 + 8;
#pragma unroll
        for (int n = 0; n < 4; n++) {
            int c = col0 + warp_n * 32 + n * 8 + lr * 2;
            if (r0 < M) {
                float2 v; v.x = acc[m][n][0]; v.y = acc[m][n][1];
                *(float2*)(out + (size_t)r0 * ldN + c) = v;
            }
            if (r1 < M) {
                float2 v; v.x = acc[m][n][2]; v.y = acc[m][n][3];
                *(float2*)(out + (size_t)r1 * ldN + c) = v;
            }
        }
    }
}

// ------- layer-1 gather + fused activation (C=128), per-edge dinv scale ----
__global__ void k_gather_act128(const float* __restrict__ g, const int* __restrict__ col,
                                const int* __restrict__ cnt, const float* __restrict__ dinv,
                                const float* __restrict__ bias,
                                float* __restrict__ out, int N) {
    int warp = (blockIdx.x * blockDim.x + threadIdx.x) >> 5;
    int lane = threadIdx.x & 31;
    pdl_wait();
    if (warp >= N) return;
    const int* bucket = col + (size_t)warp * BUCKET_CAP;
    int m = cnt[warp];
    if (m > BUCKET_CAP) m = BUCKET_CAP;

    float4 acc = make_float4(0.f, 0.f, 0.f, 0.f);
    int e = 0;
    for (; e + 4 <= m; e += 4) {
        int s0 = __ldg(&bucket[e + 0]);
        int s1 = __ldg(&bucket[e + 1]);
        int s2 = __ldg(&bucket[e + 2]);
        int s3 = __ldg(&bucket[e + 3]);
        float d0 = __ldg(&dinv[s0]);
        float d1 = __ldg(&dinv[s1]);
        float d2 = __ldg(&dinv[s2]);
        float d3 = __ldg(&dinv[s3]);
        float4 v0 = *((const float4*)(g + (size_t)s0 * 128) + lane);
        float4 v1 = *((const float4*)(g + (size_t)s1 * 128) + lane);
        float4 v2 = *((const float4*)(g + (size_t)s2 * 128) + lane);
        float4 v3 = *((const float4*)(g + (size_t)s3 * 128) + lane);
        acc.x += d0 * v0.x + d1 * v1.x + d2 * v2.x + d3 * v3.x;
        acc.y += d0 * v0.y + d1 * v1.y + d2 * v2.y + d3 * v3.y;
        acc.z += d0 * v0.z + d1 * v1.z + d2 * v2.z + d3 * v3.z;
        acc.w += d0 * v0.w + d1 * v1.w + d2 * v2.w + d3 * v3.w;
    }
    for (; e < m; e++) {
        int s = __ldg(&bucket[e]);
        float d = __ldg(&dinv[s]);
        float4 v = *((const float4*)(g + (size_t)s * 128) + lane);
        acc.x += d * v.x; acc.y += d * v.y; acc.z += d * v.z; acc.w += d * v.w;
    }
    float4 self = *((const float4*)(g + (size_t)warp * 128) + lane);
    float  dv = dinv[warp];
    float4 bb = *((const float4*)bias + lane);
    float4 r;
    r.x = tanhf((acc.x + dv * self.x) * dv + bb.x);
    r.y = tanhf((acc.y + dv * self.y) * dv + bb.y);
    r.z = tanhf((acc.z + dv * self.z) * dv + bb.z);
    r.w = tanhf((acc.w + dv * self.w) * dv + bb.w);
    *((float4*)(out + (size_t)warp * 128) + lane) = r;
}

// ------- layer-2 gather + activation + FUSED W3 matvec (C=64) --------------
__global__ void k_gather_act64_mv(const float* __restrict__ g, const int* __restrict__ col,
                                  const int* __restrict__ cnt, const float* __restrict__ dinv,
                                  const float* __restrict__ bias,
                                  const float* __restrict__ W3,
                                  float* __restrict__ u3, int N) {
    int warp = (blockIdx.x * blockDim.x + threadIdx.x) >> 5;
    int lane = threadIdx.x & 31;
    pdl_wait();
    if (warp >= N) return;
    const int* bucket = col + (size_t)warp * BUCKET_CAP;
    int m = cnt[warp];
    if (m > BUCKET_CAP) m = BUCKET_CAP;

    float2 acc = make_float2(0.f, 0.f);
    int e = 0;
    for (; e + 4 <= m; e += 4) {
        int s0 = __ldg(&bucket[e + 0]);
        int s1 = __ldg(&bucket[e + 1]);
        int s2 = __ldg(&bucket[e + 2]);
        int s3 = __ldg(&bucket[e + 3]);
        float d0 = __ldg(&dinv[s0]);
        float d1 = __ldg(&dinv[s1]);
        float d2 = __ldg(&dinv[s2]);
        float d3 = __ldg(&dinv[s3]);
        float2 v0 = *((const float2*)(g + (size_t)s0 * 64) + lane);
        float2 v1 = *((const float2*)(g + (size_t)s1 * 64) + lane);
        float2 v2 = *((const float2*)(g + (size_t)s2 * 64) + lane);
        float2 v3 = *((const float2*)(g + (size_t)s3 * 64) + lane);
        acc.x += d0 * v0.x + d1 * v1.x + d2 * v2.x + d3 * v3.x;
        acc.y += d0 * v0.y + d1 * v1.y + d2 * v2.y + d3 * v3.y;
    }
    for (; e < m; e++) {
        int s = __ldg(&bucket[e]);
        float d = __ldg(&dinv[s]);
        float2 v = *((const float2*)(g + (size_t)s * 64) + lane);
        acc.x += d * v.x; acc.y += d * v.y;
    }
    float2 self = *((const float2*)(g + (size_t)warp * 64) + lane);
    float  dv = dinv[warp];
    float2 bb = *((const float2*)bias + lane);
    float hx = tanhf((acc.x + dv * self.x) * dv + bb.x);
    float hy = tanhf((acc.y + dv * self.y) * dv + bb.y);
    float2 w = *((const float2*)W3 + lane);
    float s = hx * w.x + hy * w.y;
#pragma unroll
    for (int o = 16; o; o >>= 1) s += __shfl_xor_sync(0xFFFFFFFFu, s, o);
    if (lane == 0) u3[warp] = s * dv;   // u3 = dinv * (h2 . W3)
}

// ------- layer3 gather + activation + dot with W4, atomic into d_out -------
__global__ void k_gather3_dot(const float* __restrict__ u3, const int* __restrict__ col,
                              const int* __restrict__ cnt, const float* __restrict__ dinv,
                              const float* __restrict__ b3,
                              const float* __restrict__ W4, float* __restrict__ out,
                              int N) {
    __shared__ float sm[256];
    int i = blockIdx.x * 256 + threadIdx.x;
    pdl_wait();
    float contrib = 0.0f;
    if (i < N) {
        const int* bucket = col + (size_t)i * BUCKET_CAP;
        int m = cnt[i];
        if (m > BUCKET_CAP) m = BUCKET_CAP;
        float acc = 0.0f;
        for (int e = 0; e < m; e++) acc += u3[__ldg(&bucket[e])];
        float v = tanhf((acc + u3[i]) * dinv[i] + b3[0]);
        contrib = W4[i] * v;
    }
    sm[threadIdx.x] = contrib;
    __syncthreads();
    for (int s = 128; s; s >>= 1) {
        if (threadIdx.x < s) sm[threadIdx.x] += sm[threadIdx.x + s];
        __syncthreads();
    }
    if (threadIdx.x == 0) atomicAdd(out, sm[0]);
}

// ---------------------------------------------------------------------------
extern "C" void kernel_launch(void* const* d_in, const int* in_sizes, int n_in,
                              void* d_out, int out_size) {
    const float* x   = (const float*)d_in[0];
    const int*   ei  = (const int*)d_in[1];
    const float* W1  = (const float*)d_in[2];
    const float* b1  = (const float*)d_in[3];
    const float* W2  = (const float*)d_in[4];
    const float* b2  = (const float*)d_in[5];
    const float* W3  = (const float*)d_in[6];
    const float* b3  = (const float*)d_in[7];
    const float* W4  = (const float*)d_in[8];
    const float* b4  = (const float*)d_in[9];

    int N = in_sizes[0] / 128;
    int E = in_sizes[1] / 2;
    const int* src = ei;
    const int* dst = ei + E;

    int *cnt, *col;
    float *dinv, *bufA, *bufB, *bufC;
    cudaGetSymbolAddress((void**)&cnt, g_cnt);
    cudaGetSymbolAddress((void**)&col, g_col);
    cudaGetSymbolAddress((void**)&dinv, g_dinv);
    cudaGetSymbolAddress((void**)&bufA, g_bufA);
    cudaGetSymbolAddress((void**)&bufB, g_bufB);
    cudaGetSymbolAddress((void**)&bufC, g_bufC);

    const int nBlkN = (N + 255) / 256;
    const int rowBlk = (N + 127) / 128;

    // One-time side stream + fork/join events (infrastructure, not work).
    static cudaStream_t s_side = nullptr;
    static cudaEvent_t  ev_fork = nullptr, ev_join = nullptr;
    if (s_side == nullptr) {
        cudaStreamCreateWithFlags(&s_side, cudaStreamNonBlocking);
        cudaEventCreateWithFlags(&ev_fork, cudaEventDisableTiming);
        cudaEventCreateWithFlags(&ev_join, cudaEventDisableTiming);
    }

    // PDL launch config (programmatic serialization with stream predecessor)
    cudaLaunchAttribute pdlAttr[1];
    pdlAttr[0].id = cudaLaunchAttributeProgrammaticStreamSerialization;
    pdlAttr[0].val.programmaticStreamSerializationAllowed = 1;

    // ---- fork: CSR build on side stream, gemm1 on main stream ----
    cudaEventRecord(ev_fork, 0);
    cudaStreamWaitEvent(s_side, ev_fork, 0);
    k_zero_int<<<nBlkN, 256, 0, s_side>>>(cnt, N);
    k_fillcount<<<(E + 255) / 256, 256, 0, s_side>>>(src, dst, E, cnt, col);
    k_dinv<<<nBlkN, 256, 0, s_side>>>(cnt, dinv, N, b4, (float*)d_out);
    cudaEventRecord(ev_join, s_side);

    // ---- layer 1 (128 -> 128), independent of CSR ----
    k_gemm_bf16x3<<<dim3(rowBlk, 2), 128>>>(x, W1, bufA, N, 128);           // g1

    // ---- join: gathers need CSR ----
    cudaStreamWaitEvent(0, ev_join, 0);
    {
        cudaLaunchConfig_t cfg = {};
        cfg.gridDim = dim3((N * 32 + 255) / 256);
        cfg.blockDim = dim3(256);
        cfg.attrs = pdlAttr; cfg.numAttrs = 1;
        cudaLaunchKernelEx(&cfg, k_gather_act128, (const float*)bufA, (const int*)col,
                           (const int*)cnt, (const float*)dinv, b1, bufB, N);  // h1
    }

    // ---- layer 2 (128 -> 64) + fused layer-3 matvec ----
    {
        cudaLaunchConfig_t cfg = {};
        cfg.gridDim = dim3(rowBlk, 1);
        cfg.blockDim = dim3(128);
        cfg.attrs = pdlAttr; cfg.numAttrs = 1;
        cudaLaunchKernelEx(&cfg, k_gemm_bf16x3, (const float*)bufB, W2, bufC, N, 64);  // g2
    }
    {
        cudaLaunchConfig_t cfg = {};
        cfg.gridDim = dim3((N * 32 + 255) / 256);
        cfg.blockDim = dim3(256);
        cfg.attrs = pdlAttr; cfg.numAttrs = 1;
        cudaLaunchKernelEx(&cfg, k_gather_act64_mv, (const float*)bufC, (const int*)col,
                           (const int*)cnt, (const float*)dinv, b2, W3, bufA, N);  // u3
    }

    // ---- layer 3 aggregation + final dot (atomic into seeded d_out) ----
    {
        cudaLaunchConfig_t cfg = {};
        cfg.gridDim = dim3(nBlkN);
        cfg.blockDim = dim3(256);
        cfg.attrs = pdlAttr; cfg.numAttrs = 1;
        cudaLaunchKernelEx(&cfg, k_gather3_dot, (const float*)bufA, (const int*)col,
                           (const int*)cnt, (const float*)dinv, b3, W4,
                           (float*)d_out, N);
    }
}

// round 17
// speedup vs baseline: 1.0925x; 1.0005x over previous
#include <cuda_runtime.h>
#include <cuda_bf16.h>
#include <cstddef>
#include <cstdint>

// ---------------------------------------------------------------------------
// GCN_ValueNet: 3-layer GCN (128->128->64->1) + final dot with W4.
//   g = X@W  raw, via bf16x3 emulated-fp32 GEMM on m16n8k16 bf16 tensor cores:
//     x = h + m,  h = bf16(x), m = bf16(x - h)  (residual ~2^-18)
//     D += ah*bh + am*bh + ah*bm    (fp32 accumulate, phase-ordered)
//   GEMM: 128 thr / 4 warps (2Mx2N), warp tile 64x32, DOUBLE-BUFFERED smem
//         (one __syncthreads per k-tile; STS overlaps the MMA block).
//   gathers apply symmetric normalization per-edge.
//   CSR build (bucket, cap 64) on a SIDE STREAM hidden under gemm1; k_dinv
//   also seeds d_out[0] = b4[0] so the last gather atomically accumulates
//   the final dot directly into d_out (no separate reduce kernel).
//   Dependent kernels use PDL (griddepcontrol.wait) to absorb launch gaps.
// edge_index arrives as int32 (JAX x64 disabled).
// NOTE: tcgen05 unavailable (harness PTX target is compute_103, no 'a').
// ---------------------------------------------------------------------------

#define MAX_NODES 50016
#define BUCKET_CAP 64

__device__ int   g_cnt[MAX_NODES];
__device__ int   g_col[MAX_NODES * BUCKET_CAP];
__device__ float g_dinv[MAX_NODES];
__device__ float g_bufA[MAX_NODES * 128];
__device__ float g_bufB[MAX_NODES * 128];
__device__ float g_bufC[MAX_NODES * 128];

__device__ __forceinline__ void pdl_wait() {
    asm volatile("griddepcontrol.wait;" ::: "memory");
}

// Pack two consecutive elements (x0 = even-k, x1 = odd-k) into (h, m) bf16x2.
__device__ __forceinline__ uint2 pack_hm(float x0, float x1) {
    uint32_t hp;
    asm("cvt.rn.bf16x2.f32 %0, %1, %2;" : "=r"(hp) : "f"(x1), "f"(x0));
    float h0 = __uint_as_float(hp << 16);
    float h1 = __uint_as_float(hp & 0xFFFF0000u);
    uint32_t mp;
    asm("cvt.rn.bf16x2.f32 %0, %1, %2;" : "=r"(mp) : "f"(x1 - h1), "f"(x0 - h0));
    return make_uint2(hp, mp);
}

__device__ __forceinline__ void mma_bf16(float* d, const uint32_t* a,
                                         const uint32_t* b, const float* c) {
    asm("mma.sync.aligned.m16n8k16.row.col.f32.bf16.bf16.f32 "
        "{%0,%1,%2,%3},{%4,%5,%6,%7},{%8,%9},{%10,%11,%12,%13};"
        : "=f"(d[0]), "=f"(d[1]), "=f"(d[2]), "=f"(d[3])
        : "r"(a[0]), "r"(a[1]), "r"(a[2]), "r"(a[3]),
          "r"(b[0]), "r"(b[1]),
          "f"(c[0]), "f"(c[1]), "f"(c[2]), "f"(c[3]));
}

// ---------------- bucket-CSR build ----------------
__global__ void k_zero_int(int* p, int n) {
    int i = blockIdx.x * blockDim.x + threadIdx.x;
    if (i < n) p[i] = 0;
}

__global__ void k_fillcount(const int* __restrict__ src, const int* __restrict__ dst,
                            int E, int* __restrict__ cnt, int* __restrict__ col) {
    int i = blockIdx.x * blockDim.x + threadIdx.x;
    if (i >= E) return;
    int d = dst[i];
    int slot = atomicAdd(&cnt[d], 1);
    if (slot < BUCKET_CAP) col[d * BUCKET_CAP + slot] = src[i];
}

// dinv + seed d_out[0] = b4[0] (reset every replay; stream order guarantees
// this happens before k_gather3_dot's atomic accumulation).
__global__ void k_dinv(const int* __restrict__ cnt, float* __restrict__ dinv, int n,
                       const float* __restrict__ b4, float* __restrict__ out0) {
    int i = blockIdx.x * blockDim.x + threadIdx.x;
    if (i < n) dinv[i] = rsqrtf((float)cnt[i] + 1.0f);
    if (i == 0) out0[0] = b4[0];
}

// ------- bf16x3 GEMM: out[r][col0+c] = A[r][:128] . W[:][col0+c] ------------
// BM=128, BN=64 per CTA (blockIdx.y = col block), BK=16 (one k16 step per kt).
// 128 threads = 4 warps as 2(M) x 2(N); warp tile 64x32 = 4 mtiles x 4 ntiles.
// Double-buffered smem: MMA(buf) overlaps split+STS(buf^1); one sync per kt.
__global__ __launch_bounds__(128, 3) void k_gemm_bf16x3(const float* __restrict__ A,
                                                        const float* __restrict__ W,
                                                        float* __restrict__ out,
                                                        int M, int ldN) {
    constexpr int BM = 128, BN = 64, BK = 16, K = 128;
    constexpr int SAS = 10;   // uint2/row: 8 k-pairs + 2 pad
    constexpr int SBS = 68;   // uint2/k-pair row: 64 n + 4 pad
    __shared__ uint2 sA[2][BM][SAS];      // 20.0 KB
    __shared__ uint2 sB[2][BK / 2][SBS];  //  8.5 KB

    pdl_wait();   // no-op when launched without the PDL attribute

    const int tid    = threadIdx.x;
    const int wid    = tid >> 5;
    const int lane   = tid & 31;
    const int warp_m = wid & 1;
    const int warp_n = wid >> 1;
    const int row0   = blockIdx.x * BM;
    const int col0   = blockIdx.y * BN;

    float acc[4][4][4];
#pragma unroll
    for (int m = 0; m < 4; m++)
#pragma unroll
        for (int n = 0; n < 4; n++)
#pragma unroll
            for (int q = 0; q < 4; q++) acc[m][n][q] = 0.0f;

    const int aRow  = tid >> 2;           // 0..31
    const int aColE = (tid & 3) * 4;      // element k-offset 0,4,8,12
    const int aPair = (tid & 3) * 2;      // pair index 0,2,4,6
    const int bKp = tid >> 4;             // 0..7
    const int bN0 = (tid & 15) * 4;       // 0..60

    bool aOk[4];
    const float* aP[4];
#pragma unroll
    for (int p = 0; p < 4; p++) {
        int r = row0 + aRow + p * 32;
        aOk[p] = r < M;
        aP[p]  = A + (size_t)r * K + aColE;
    }
    const float* bP0 = W + (size_t)(2 * bKp)     * ldN + col0 + bN0;
    const float* bP1 = W + (size_t)(2 * bKp + 1) * ldN + col0 + bN0;

    const int lq = lane >> 2;             // 0..7
    const int lr = lane & 3;              // 0..3

    // ---- prologue: load + store kt = 0 into buffer 0 ----
    float4 pa[4], pb0, pb1;
#pragma unroll
    for (int p = 0; p < 4; p++) {
        pa[p] = make_float4(0.f, 0.f, 0.f, 0.f);
        if (aOk[p]) pa[p] = *(const float4*)aP[p];
    }
    pb0 = *(const float4*)bP0;
    pb1 = *(const float4*)bP1;
#pragma unroll
    for (int p = 0; p < 4; p++) {
        uint2 e0 = pack_hm(pa[p].x, pa[p].y);
        uint2 e1 = pack_hm(pa[p].z, pa[p].w);
        *(uint4*)&sA[0][aRow + p * 32][aPair] = make_uint4(e0.x, e0.y, e1.x, e1.y);
    }
    {
        uint2 e0 = pack_hm(pb0.x, pb1.x);
        uint2 e1 = pack_hm(pb0.y, pb1.y);
        uint2 e2 = pack_hm(pb0.z, pb1.z);
        uint2 e3 = pack_hm(pb0.w, pb1.w);
        *(uint4*)&sB[0][bKp][bN0    ] = make_uint4(e0.x, e0.y, e1.x, e1.y);
        *(uint4*)&sB[0][bKp][bN0 + 2] = make_uint4(e2.x, e2.y, e3.x, e3.y);
    }
    __syncthreads();

    int buf = 0;
#pragma unroll
    for (int kt = 0; kt < K / BK; kt++) {
        const bool more = kt < K / BK - 1;
        // prefetch kt+1 from gmem (latency hides under the MMA block below)
        if (more) {
            const int k0 = (kt + 1) * BK;
#pragma unroll
            for (int p = 0; p < 4; p++) {
                pa[p] = make_float4(0.f, 0.f, 0.f, 0.f);
                if (aOk[p]) pa[p] = *(const float4*)(aP[p] + k0);
            }
            pb0 = *(const float4*)(bP0 + (size_t)k0 * ldN);
            pb1 = *(const float4*)(bP1 + (size_t)k0 * ldN);
        }

        // MMA on current buffer (one m16n8k16 step covers BK=16)
        {
            uint32_t ah[4][4], am[4][4], bh[4][2], bm[4][2];
#pragma unroll
            for (int m = 0; m < 4; m++) {
                int r = warp_m * 64 + m * 16 + lq;
                uint2 q0 = sA[buf][r    ][lr    ];
                uint2 q1 = sA[buf][r + 8][lr    ];
                uint2 q2 = sA[buf][r    ][lr + 4];
                uint2 q3 = sA[buf][r + 8][lr + 4];
                ah[m][0] = q0.x; ah[m][1] = q1.x; ah[m][2] = q2.x; ah[m][3] = q3.x;
                am[m][0] = q0.y; am[m][1] = q1.y; am[m][2] = q2.y; am[m][3] = q3.y;
            }
#pragma unroll
            for (int n = 0; n < 4; n++) {
                int c = warp_n * 32 + n * 8 + lq;
                uint2 p0 = sB[buf][lr    ][c];
                uint2 p1 = sB[buf][lr + 4][c];
                bh[n][0] = p0.x; bh[n][1] = p1.x;
                bm[n][0] = p0.y; bm[n][1] = p1.y;
            }
#pragma unroll
            for (int n = 0; n < 4; n++)
#pragma unroll
                for (int m = 0; m < 4; m++)
                    mma_bf16(acc[m][n], ah[m], bh[n], acc[m][n]);
#pragma unroll
            for (int n = 0; n < 4; n++)
#pragma unroll
                for (int m = 0; m < 4; m++)
                    mma_bf16(acc[m][n], am[m], bh[n], acc[m][n]);
#pragma unroll
            for (int n = 0; n < 4; n++)
#pragma unroll
                for (int m = 0; m < 4; m++)
                    mma_bf16(acc[m][n], ah[m], bm[n], acc[m][n]);
        }

        // split + store kt+1 into the other buffer (overlaps MMA tail)
        if (more) {
#pragma unroll
            for (int p = 0; p < 4; p++) {
                uint2 e0 = pack_hm(pa[p].x, pa[p].y);
                uint2 e1 = pack_hm(pa[p].z, pa[p].w);
                *(uint4*)&sA[buf ^ 1][aRow + p * 32][aPair] =
                    make_uint4(e0.x, e0.y, e1.x, e1.y);
            }
            uint2 e0 = pack_hm(pb0.x, pb1.x);
            uint2 e1 = pack_hm(pb0.y, pb1.y);
            uint2 e2 = pack_hm(pb0.z, pb1.z);
            uint2 e3 = pack_hm(pb0.w, pb1.w);
            *(uint4*)&sB[buf ^ 1][bKp][bN0    ] = make_uint4(e0.x, e0.y, e1.x, e1.y);
            *(uint4*)&sB[buf ^ 1][bKp][bN0 + 2] = make_uint4(e2.x, e2.y, e3.x, e3.y);
            __syncthreads();
            buf ^= 1;
        }
    }

    // epilogue: store raw g (normalization applied in the gather kernels)
#pragma unroll
    for (int m = 0; m < 4; m++) {
        int r0 = row0 + warp_m * 64 + m * 16 + lq;
        int r1 = r0 + 8;
#pragma unroll
        for (int n = 0; n < 4; n++) {
            int c = col0 + warp_n * 32 + n * 8 + lr * 2;
            if (r0 < M) {
                float2 v; v.x = acc[m][n][0]; v.y = acc[m][n][1];
                *(float2*)(out + (size_t)r0 * ldN + c) = v;
            }
            if (r1 < M) {
                float2 v; v.x = acc[m][n][2]; v.y = acc[m][n][3];
                *(float2*)(out + (size_t)r1 * ldN + c) = v;
            }
        }
    }
}

// ------- layer-1 gather + fused activation (C=128), per-edge dinv scale ----
__global__ void k_gather_act128(const float* __restrict__ g, const int* __restrict__ col,
                                const int* __restrict__ cnt, const float* __restrict__ dinv,
                                const float* __restrict__ bias,
                                float* __restrict__ out, int N) {
    int warp = (blockIdx.x * blockDim.x + threadIdx.x) >> 5;
    int lane = threadIdx.x & 31;
    pdl_wait();
    if (warp >= N) return;
    const int* bucket = col + (size_t)warp * BUCKET_CAP;
    int m = cnt[warp];
    if (m > BUCKET_CAP) m = BUCKET_CAP;

    float4 acc = make_float4(0.f, 0.f, 0.f, 0.f);
    int e = 0;
    for (; e + 4 <= m; e += 4) {
        int s0 = __ldg(&bucket[e + 0]);
        int s1 = __ldg(&bucket[e + 1]);
        int s2 = __ldg(&bucket[e + 2]);
        int s3 = __ldg(&bucket[e + 3]);
        float d0 = __ldg(&dinv[s0]);
        float d1 = __ldg(&dinv[s1]);
        float d2 = __ldg(&dinv[s2]);
        float d3 = __ldg(&dinv[s3]);
        float4 v0 = *((const float4*)(g + (size_t)s0 * 128) + lane);
        float4 v1 = *((const float4*)(g + (size_t)s1 * 128) + lane);
        float4 v2 = *((const float4*)(g + (size_t)s2 * 128) + lane);
        float4 v3 = *((const float4*)(g + (size_t)s3 * 128) + lane);
        acc.x += d0 * v0.x + d1 * v1.x + d2 * v2.x + d3 * v3.x;
        acc.y += d0 * v0.y + d1 * v1.y + d2 * v2.y + d3 * v3.y;
        acc.z += d0 * v0.z + d1 * v1.z + d2 * v2.z + d3 * v3.z;
        acc.w += d0 * v0.w + d1 * v1.w + d2 * v2.w + d3 * v3.w;
    }
    for (; e < m; e++) {
        int s = __ldg(&bucket[e]);
        float d = __ldg(&dinv[s]);
        float4 v = *((const float4*)(g + (size_t)s * 128) + lane);
        acc.x += d * v.x; acc.y += d * v.y; acc.z += d * v.z; acc.w += d * v.w;
    }
    float4 self = *((const float4*)(g + (size_t)warp * 128) + lane);
    float  dv = dinv[warp];
    float4 bb = *((const float4*)bias + lane);
    float4 r;
    r.x = tanhf((acc.x + dv * self.x) * dv + bb.x);
    r.y = tanhf((acc.y + dv * self.y) * dv + bb.y);
    r.z = tanhf((acc.z + dv * self.z) * dv + bb.z);
    r.w = tanhf((acc.w + dv * self.w) * dv + bb.w);
    *((float4*)(out + (size_t)warp * 128) + lane) = r;
}

// ------- layer-2 gather + activation + FUSED W3 matvec (C=64) --------------
__global__ void k_gather_act64_mv(const float* __restrict__ g, const int* __restrict__ col,
                                  const int* __restrict__ cnt, const float* __restrict__ dinv,
                                  const float* __restrict__ bias,
                                  const float* __restrict__ W3,
                                  float* __restrict__ u3, int N) {
    int warp = (blockIdx.x * blockDim.x + threadIdx.x) >> 5;
    int lane = threadIdx.x & 31;
    pdl_wait();
    if (warp >= N) return;
    const int* bucket = col + (size_t)warp * BUCKET_CAP;
    int m = cnt[warp];
    if (m > BUCKET_CAP) m = BUCKET_CAP;

    float2 acc = make_float2(0.f, 0.f);
    int e = 0;
    for (; e + 4 <= m; e += 4) {
        int s0 = __ldg(&bucket[e + 0]);
        int s1 = __ldg(&bucket[e + 1]);
        int s2 = __ldg(&bucket[e + 2]);
        int s3 = __ldg(&bucket[e + 3]);
        float d0 = __ldg(&dinv[s0]);
        float d1 = __ldg(&dinv[s1]);
        float d2 = __ldg(&dinv[s2]);
        float d3 = __ldg(&dinv[s3]);
        float2 v0 = *((const float2*)(g + (size_t)s0 * 64) + lane);
        float2 v1 = *((const float2*)(g + (size_t)s1 * 64) + lane);
        float2 v2 = *((const float2*)(g + (size_t)s2 * 64) + lane);
        float2 v3 = *((const float2*)(g + (size_t)s3 * 64) + lane);
        acc.x += d0 * v0.x + d1 * v1.x + d2 * v2.x + d3 * v3.x;
        acc.y += d0 * v0.y + d1 * v1.y + d2 * v2.y + d3 * v3.y;
    }
    for (; e < m; e++) {
        int s = __ldg(&bucket[e]);
        float d = __ldg(&dinv[s]);
        float2 v = *((const float2*)(g + (size_t)s * 64) + lane);
        acc.x += d * v.x; acc.y += d * v.y;
    }
    float2 self = *((const float2*)(g + (size_t)warp * 64) + lane);
    float  dv = dinv[warp];
    float2 bb = *((const float2*)bias + lane);
    float hx = tanhf((acc.x + dv * self.x) * dv + bb.x);
    float hy = tanhf((acc.y + dv * self.y) * dv + bb.y);
    float2 w = *((const float2*)W3 + lane);
    float s = hx * w.x + hy * w.y;
#pragma unroll
    for (int o = 16; o; o >>= 1) s += __shfl_xor_sync(0xFFFFFFFFu, s, o);
    if (lane == 0) u3[warp] = s * dv;   // u3 = dinv * (h2 . W3)
}

// ------- layer3 gather + activation + dot with W4, atomic into d_out -------
__global__ void k_gather3_dot(const float* __restrict__ u3, const int* __restrict__ col,
                              const int* __restrict__ cnt, const float* __restrict__ dinv,
                              const float* __restrict__ b3,
                              const float* __restrict__ W4, float* __restrict__ out,
                              int N) {
    __shared__ float sm[256];
    int i = blockIdx.x * 256 + threadIdx.x;
    pdl_wait();
    float contrib = 0.0f;
    if (i < N) {
        const int* bucket = col + (size_t)i * BUCKET_CAP;
        int m = cnt[i];
        if (m > BUCKET_CAP) m = BUCKET_CAP;
        float acc = 0.0f;
        for (int e = 0; e < m; e++) acc += u3[__ldg(&bucket[e])];
        float v = tanhf((acc + u3[i]) * dinv[i] + b3[0]);
        contrib = W4[i] * v;
    }
    sm[threadIdx.x] = contrib;
    __syncthreads();
    for (int s = 128; s; s >>= 1) {
        if (threadIdx.x < s) sm[threadIdx.x] += sm[threadIdx.x + s];
        __syncthreads();
    }
    if (threadIdx.x == 0) atomicAdd(out, sm[0]);
}

// ---------------------------------------------------------------------------
extern "C" void kernel_launch(void* const* d_in, const int* in_sizes, int n_in,
                              void* d_out, int out_size) {
    const float* x   = (const float*)d_in[0];
    const int*   ei  = (const int*)d_in[1];
    const float* W1  = (const float*)d_in[2];
    const float* b1  = (const float*)d_in[3];
    const float* W2  = (const float*)d_in[4];
    const float* b2  = (const float*)d_in[5];
    const float* W3  = (const float*)d_in[6];
    const float* b3  = (const float*)d_in[7];
    const float* W4  = (const float*)d_in[8];
    const float* b4  = (const float*)d_in[9];

    int N = in_sizes[0] / 128;
    int E = in_sizes[1] / 2;
    const int* src = ei;
    const int* dst = ei + E;

    int *cnt, *col;
    float *dinv, *bufA, *bufB, *bufC;
    cudaGetSymbolAddress((void**)&cnt, g_cnt);
    cudaGetSymbolAddress((void**)&col, g_col);
    cudaGetSymbolAddress((void**)&dinv, g_dinv);
    cudaGetSymbolAddress((void**)&bufA, g_bufA);
    cudaGetSymbolAddress((void**)&bufB, g_bufB);
    cudaGetSymbolAddress((void**)&bufC, g_bufC);

    const int nBlkN = (N + 255) / 256;
    const int rowBlk = (N + 127) / 128;

    // One-time side stream + fork/join events (infrastructure, not work).
    static cudaStream_t s_side = nullptr;
    static cudaEvent_t  ev_fork = nullptr, ev_join = nullptr;
    if (s_side == nullptr) {
        cudaStreamCreateWithFlags(&s_side, cudaStreamNonBlocking);
        cudaEventCreateWithFlags(&ev_fork, cudaEventDisableTiming);
        cudaEventCreateWithFlags(&ev_join, cudaEventDisableTiming);
    }

    // PDL launch config (programmatic serialization with stream predecessor)
    cudaLaunchAttribute pdlAttr[1];
    pdlAttr[0].id = cudaLaunchAttributeProgrammaticStreamSerialization;
    pdlAttr[0].val.programmaticStreamSerializationAllowed = 1;

    // ---- fork: CSR build on side stream, gemm1 on main stream ----
    cudaEventRecord(ev_fork, 0);
    cudaStreamWaitEvent(s_side, ev_fork, 0);
    k_zero_int<<<nBlkN, 256, 0, s_side>>>(cnt, N);
    k_fillcount<<<(E + 255) / 256, 256, 0, s_side>>>(src, dst, E, cnt, col);
    k_dinv<<<nBlkN, 256, 0, s_side>>>(cnt, dinv, N, b4, (float*)d_out);
    cudaEventRecord(ev_join, s_side);

    // ---- layer 1 (128 -> 128), independent of CSR ----
    k_gemm_bf16x3<<<dim3(rowBlk, 2), 128>>>(x, W1, bufA, N, 128);           // g1

    // ---- join: gathers need CSR ----
    cudaStreamWaitEvent(0, ev_join, 0);
    {
        cudaLaunchConfig_t cfg = {};
        cfg.gridDim = dim3((N * 32 + 255) / 256);
        cfg.blockDim = dim3(256);
        cfg.attrs = pdlAttr; cfg.numAttrs = 1;
        cudaLaunchKernelEx(&cfg, k_gather_act128, (const float*)bufA, (const int*)col,
                           (const int*)cnt, (const float*)dinv, b1, bufB, N);  // h1
    }

    // ---- layer 2 (128 -> 64) + fused layer-3 matvec ----
    {
        cudaLaunchConfig_t cfg = {};
        cfg.gridDim = dim3(rowBlk, 1);
        cfg.blockDim = dim3(128);
        cfg.attrs = pdlAttr; cfg.numAttrs = 1;
        cudaLaunchKernelEx(&cfg, k_gemm_bf16x3, (const float*)bufB, W2, bufC, N, 64);  // g2
    }
    {
        cudaLaunchConfig_t cfg = {};
        cfg.gridDim = dim3((N * 32 + 255) / 256);
        cfg.blockDim = dim3(256);
        cfg.attrs = pdlAttr; cfg.numAttrs = 1;
        cudaLaunchKernelEx(&cfg, k_gather_act64_mv, (const float*)bufC, (const int*)col,
                           (const int*)cnt, (const float*)dinv, b2, W3, bufA, N);  // u3
    }

    // ---- layer 3 aggregation + final dot (atomic into seeded d_out) ----
    {
        cudaLaunchConfig_t cfg = {};
        cfg.gridDim = dim3(nBlkN);
        cfg.blockDim = dim3(256);
        cfg.attrs = pdlAttr; cfg.numAttrs = 1;
        cudaLaunchKernelEx(&cfg, k_gather3_dot, (const float*)bufA, (const int*)col,
                           (const int*)cnt, (const float*)dinv, b3, W4,
                           (float*)d_out, N);
    }
}